// round 2
// baseline (speedup 1.0000x reference)
#include <cuda_runtime.h>
#include <math.h>

#define B_   16
#define L_   512
#define HID_ 768
#define HEADS_ 12
#define M_   4
#define EMB_ 768
#define BLK_ 8
#define NER_ 6
#define NCLS_ 97
#define XDIM_ (2*HID_ + NER_)   // 1542
#define XPAD2_ 1600             // padded stride for smem tiles (25 x 64)
#define NCHUNK_ 16              // K2 l-splits

// ---------------- scratch (no allocation allowed) ----------------
__device__ float g_hs [B_*HID_];
__device__ float g_ts [B_*HID_];
__device__ float g_ht [B_*L_];
__device__ float g_htp[B_*HEADS_*L_];          // per-head ht partials
__device__ float g_rs [B_*HID_];
__device__ float g_rsp[NCHUNK_*B_*HID_];       // per-chunk rs partials
__device__ float g_hs2[B_*EMB_];
__device__ float g_ts2[B_*EMB_];

// ---------------- KB: per-(b,h) ht partial + lse (grid = B x HEADS) ----------------
__global__ void kb_gather(const float* __restrict__ seq,
                          const float* __restrict__ attn,
                          const int*   __restrict__ epos)
{
    const int b   = blockIdx.x;
    const int h   = blockIdx.y;
    const int tid = threadIdx.x;   // 256

    __shared__ int s_start[8];
    if (tid < 8) s_start[tid] = epos[b*8 + tid] + 1;
    __syncthreads();

    int s0[M_], s1[M_];
#pragma unroll
    for (int m = 0; m < M_; m++) { s0[m] = s_start[m]; s1[m] = s_start[4+m]; }

    // ht partial for this head: (mean_m a[s0]) * (mean_m a[s1]) / HEADS
    const float* ah = attn + ((size_t)b * HEADS_ + h) * L_ * L_;
#pragma unroll
    for (int r = 0; r < 2; r++) {
        const int l = tid + r*256;
        float a0 = 0.f, a1 = 0.f;
#pragma unroll
        for (int m = 0; m < M_; m++) {
            a0 += __ldg(&ah[(size_t)s0[m]*L_ + l]);
            a1 += __ldg(&ah[(size_t)s1[m]*L_ + l]);
        }
        g_htp[(b*HEADS_ + h)*L_ + l] = a0 * a1 * (1.0f/(16.0f*HEADS_));
    }

    // h==0 block also computes the entity logsumexp embeddings
    if (h == 0) {
        const float* seqb = seq + (size_t)b * L_ * HID_;
        for (int d = tid; d < HID_; d += 256) {
            float v0[M_], v1[M_];
#pragma unroll
            for (int m = 0; m < M_; m++) {
                v0[m] = __ldg(&seqb[(size_t)s0[m]*HID_ + d]);
                v1[m] = __ldg(&seqb[(size_t)s1[m]*HID_ + d]);
            }
            float mx0 = fmaxf(fmaxf(v0[0], v0[1]), fmaxf(v0[2], v0[3]));
            float mx1 = fmaxf(fmaxf(v1[0], v1[1]), fmaxf(v1[2], v1[3]));
            float e0 = expf(v0[0]-mx0)+expf(v0[1]-mx0)+expf(v0[2]-mx0)+expf(v0[3]-mx0);
            float e1 = expf(v1[0]-mx1)+expf(v1[1]-mx1)+expf(v1[2]-mx1)+expf(v1[3]-mx1);
            g_hs[b*HID_ + d] = mx0 + logf(e0);
            g_ts[b*HID_ + d] = mx1 + logf(e1);
        }
    }
}

// ---------------- KC: reduce heads + normalize ht (grid = B) ----------------
__global__ void kc_norm()
{
    const int b   = blockIdx.x;
    const int tid = threadIdx.x;   // 256
    __shared__ float sht[L_];
    __shared__ float sred[256];

    float lsum = 0.f;
#pragma unroll
    for (int r = 0; r < 2; r++) {
        const int l = tid + r*256;
        float acc = 0.f;
#pragma unroll
        for (int h = 0; h < HEADS_; h++)
            acc += g_htp[(b*HEADS_ + h)*L_ + l];
        sht[l] = acc;
        lsum += acc;
    }
    sred[tid] = lsum;
    __syncthreads();
    for (int s = 128; s > 0; s >>= 1) {
        if (tid < s) sred[tid] += sred[tid + s];
        __syncthreads();
    }
    const float inv = 1.0f / (sred[0] + 1e-5f);
#pragma unroll
    for (int r = 0; r < 2; r++) {
        const int l = tid + r*256;
        g_ht[b*L_ + l] = sht[l] * inv;
    }
}

// ---------------- K2: rs partials (grid = NCHUNK x B) ----------------
__global__ void k2_rs(const float* __restrict__ seq)
{
    const int b     = blockIdx.y;
    const int chunk = blockIdx.x;       // 16 chunks of 32 l
    const int tid   = threadIdx.x;      // 256, 3 dims each
    const int l0    = chunk * 32;

    const float* seqb = seq + ((size_t)b * L_ + l0) * HID_;
    const float* htb  = g_ht + b*L_ + l0;

    float a0 = 0.f, a1 = 0.f, a2 = 0.f;
#pragma unroll 8
    for (int l = 0; l < 32; l++) {
        const float w = __ldg(&htb[l]);
        const float* row = seqb + (size_t)l * HID_;
        a0 = fmaf(__ldg(&row[tid      ]), w, a0);
        a1 = fmaf(__ldg(&row[tid + 256]), w, a1);
        a2 = fmaf(__ldg(&row[tid + 512]), w, a2);
    }
    float* dst = g_rsp + ((size_t)chunk * B_ + b) * HID_;
    dst[tid      ] = a0;
    dst[tid + 256] = a1;
    dst[tid + 512] = a2;
}

// ---------------- KD: reduce rs partials (grid = B) ----------------
__global__ void kd_reduce()
{
    const int b   = blockIdx.x;
    const int tid = threadIdx.x;   // 256
#pragma unroll
    for (int r = 0; r < 3; r++) {
        const int d = tid + r*256;
        float acc = 0.f;
#pragma unroll
        for (int c = 0; c < NCHUNK_; c++)
            acc += g_rsp[((size_t)c * B_ + b)*HID_ + d];
        g_rs[b*HID_ + d] = acc;
    }
}

// ---------------- K3: hs2/ts2 = tanh(x @ W.T + b) (grid = 192) ----------------
// 8 output rows per block (1 per warp), all 16 batches.
// smem: x tile [B][XPAD2] + W tile [8][XPAD2], both zero-padded.
__global__ void __launch_bounds__(256, 1) k3_gemm(
    const float* __restrict__ Wh, const float* __restrict__ bh,
    const float* __restrict__ Wt, const float* __restrict__ bt,
    const float* __restrict__ hs_ner, const float* __restrict__ ts_ner)
{
    extern __shared__ float sm[];
    float* xsh = sm;                    // B_ * XPAD2_
    float* wsh = sm + B_*XPAD2_;        // 8 * XPAD2_

    const int half = blockIdx.x / 96;
    const int tile = blockIdx.x % 96;
    const int tid  = threadIdx.x;

    const float* Wsel = half ? Wt : Wh;
    const float* bias = half ? bt : bh;
    const float* emb  = half ? g_ts : g_hs;
    const float* ner  = half ? ts_ner : hs_ner;
    float*       outb = half ? g_ts2 : g_hs2;
    const int obase = tile * 8;

    // zero pads
    for (int i = tid; i < (B_+8)*XPAD2_; i += 256) sm[i] = 0.f;
    __syncthreads();

    // fill x
    for (int idx = tid; idx < B_*XDIM_; idx += 256) {
        const int b = idx / XDIM_;
        const int k = idx - b*XDIM_;
        float v;
        if (k < HID_)        v = emb[b*HID_ + k];
        else if (k < 2*HID_) v = g_rs[b*HID_ + (k - HID_)];
        else                 v = ner[b*NER_ + (k - 2*HID_)];
        xsh[b*XPAD2_ + k] = v;
    }
    // fill W tile (coalesced, no consumer dependency -> high MLP)
    const float* Wbase = Wsel + (size_t)obase * XDIM_;
    for (int idx = tid; idx < 8*XDIM_; idx += 256) {
        const int r = idx / XDIM_;
        const int k = idx - r*XDIM_;
        wsh[r*XPAD2_ + k] = __ldg(&Wbase[(size_t)r*XDIM_ + k]);
    }
    __syncthreads();

    const int w    = tid >> 5;
    const int lane = tid & 31;

    float acc[B_];
#pragma unroll
    for (int b = 0; b < B_; b++) acc[b] = 0.f;

    const float* wrow = wsh + w*XPAD2_;
#pragma unroll 5
    for (int it = 0; it < 25; it++) {
        const int k = lane*2 + it*64;
        const float2 wv = *(const float2*)&wrow[k];
#pragma unroll
        for (int b = 0; b < B_; b++) {
            const float2 xv = *(const float2*)&xsh[b*XPAD2_ + k];
            acc[b] = fmaf(wv.x, xv.x, acc[b]);
            acc[b] = fmaf(wv.y, xv.y, acc[b]);
        }
    }

#pragma unroll
    for (int b = 0; b < B_; b++) {
#pragma unroll
        for (int off = 16; off > 0; off >>= 1)
            acc[b] += __shfl_down_sync(0xffffffffu, acc[b], off);
    }
    if (lane == 0) {
        const int o = obase + w;
        const float bi = bias[o];
#pragma unroll
        for (int b = 0; b < B_; b++)
            outb[b*EMB_ + o] = tanhf(acc[b] + bi);
    }
}

// ---------------- K4: bilinear + logits (grid = NCLS) ----------------
// smem: hs2 [B][EMB], ts2 [B][EMB], Wc [EMB*BLK], red [8][B]
__global__ void __launch_bounds__(256, 1) k4_logits(
    const float* __restrict__ Wb, const float* __restrict__ bb,
    float* __restrict__ out)
{
    extern __shared__ float sm[];
    float* hsh = sm;                       // B_*EMB_
    float* tsh = hsh + B_*EMB_;            // B_*EMB_
    float* wsh = tsh + B_*EMB_;            // EMB_*BLK_
    float* red = wsh + EMB_*BLK_;          // 8*B_

    const int c   = blockIdx.x;
    const int tid = threadIdx.x;           // 256

    for (int i = tid; i < B_*EMB_; i += 256) {
        hsh[i] = g_hs2[i];
        tsh[i] = g_ts2[i];
    }
    const float* Wc = Wb + (size_t)c * (EMB_*BLK_);
    for (int i = tid; i < EMB_*BLK_; i += 256)
        wsh[i] = __ldg(&Wc[i]);
    __syncthreads();

    float acc[B_];
#pragma unroll
    for (int b = 0; b < B_; b++) acc[b] = 0.f;

    // pairs of consecutive j: share hidx, tidx contiguous -> float2 LDS
#pragma unroll 3
    for (int it = 0; it < 12; it++) {
        const int jj = tid*2 + it*512;
        const float2 wv = *(const float2*)&wsh[jj];
        const int hidx  = jj >> 3;
        const int tidx  = ((jj >> 6) << 3) | (jj & 7);
#pragma unroll
        for (int b = 0; b < B_; b++) {
            const float  hv = hsh[b*EMB_ + hidx];
            const float2 tv = *(const float2*)&tsh[b*EMB_ + tidx];
            acc[b] = fmaf(wv.x, hv*tv.x, acc[b]);
            acc[b] = fmaf(wv.y, hv*tv.y, acc[b]);
        }
    }

    const int w = tid >> 5, lane = tid & 31;
#pragma unroll
    for (int b = 0; b < B_; b++) {
#pragma unroll
        for (int off = 16; off > 0; off >>= 1)
            acc[b] += __shfl_down_sync(0xffffffffu, acc[b], off);
    }
    if (lane == 0) {
#pragma unroll
        for (int b = 0; b < B_; b++) red[w*B_ + b] = acc[b];
    }
    __syncthreads();
    if (tid < B_) {
        float s = bb[c];
#pragma unroll
        for (int w2 = 0; w2 < 8; w2++) s += red[w2*B_ + tid];
        out[tid*NCLS_ + c] = s;
    }
}

// ---------------- launch ----------------
extern "C" void kernel_launch(void* const* d_in, const int* in_sizes, int n_in,
                              void* d_out, int out_size)
{
    const float* seq    = (const float*)d_in[0];
    const float* attn   = (const float*)d_in[1];
    const int*   epos   = (const int*)  d_in[2];
    const float* hs_ner = (const float*)d_in[3];
    const float* ts_ner = (const float*)d_in[4];
    const float* Wh     = (const float*)d_in[5];
    const float* bh     = (const float*)d_in[6];
    const float* Wt     = (const float*)d_in[7];
    const float* bt     = (const float*)d_in[8];
    const float* Wb     = (const float*)d_in[9];
    const float* bb     = (const float*)d_in[10];
    float* out = (float*)d_out;

    const int smem_k3 = (B_ + 8) * XPAD2_ * 4;                       // 153600 B
    const int smem_k4 = (2*B_*EMB_ + EMB_*BLK_ + 8*B_) * 4;          // 123392 B
    cudaFuncSetAttribute(k3_gemm,   cudaFuncAttributeMaxDynamicSharedMemorySize, smem_k3);
    cudaFuncSetAttribute(k4_logits, cudaFuncAttributeMaxDynamicSharedMemorySize, smem_k4);

    dim3 gb(B_, HEADS_);
    kb_gather<<<gb, 256>>>(seq, attn, epos);
    kc_norm<<<B_, 256>>>();
    dim3 g2(NCHUNK_, B_);
    k2_rs<<<g2, 256>>>(seq);
    kd_reduce<<<B_, 256>>>();
    k3_gemm<<<192, 256, smem_k3>>>(Wh, bh, Wt, bt, hs_ner, ts_ner);
    k4_logits<<<NCLS_, 256, smem_k4>>>(Wb, bb, out);
}

// round 3
// speedup vs baseline: 1.7432x; 1.7432x over previous
#include <cuda_runtime.h>
#include <math.h>

#define B_    16
#define L_    512
#define HID_  768
#define HEADS_ 12
#define EMB_  768
#define BLK_  8
#define NER_  6
#define NCLS_ 97
#define XDIM_ 1542            // 2*HID + NER
#define XS_   1600            // padded stride (25 * 64)
#define NCHUNK_ 16
#define NB_   148
#define NT_   256

// ---------------- scratch (__device__ globals; no allocation) ----------------
__device__ float g_htp[B_*HEADS_*L_];      // per-head ht partials
__device__ float g_hs [B_*HID_];
__device__ float g_ts [B_*HID_];
__device__ float g_rsp[NCHUNK_*B_*HID_];   // rs chunk partials
__device__ float g_Sp [NCHUNK_*B_];        // sht chunk sums
__device__ float g_x  [2*B_*XS_];          // K3 input, padded/zero-filled
__device__ float g_hs2[B_*EMB_];
__device__ float g_ts2[B_*EMB_];
__device__ unsigned long long g_bar = 0ULL; // monotonic ticket barrier

__device__ __forceinline__ void grid_barrier() {
    __syncthreads();
    if (threadIdx.x == 0) {
        __threadfence();
        unsigned long long pos = atomicAdd(&g_bar, 1ULL);
        unsigned long long target = (pos / NB_ + 1ULL) * NB_;
        while (atomicAdd(&g_bar, 0ULL) < target) __nanosleep(64);
        __threadfence();
    }
    __syncthreads();
}

__global__ void __launch_bounds__(NT_, 1) fused_kernel(
    const float* __restrict__ seq,  const float* __restrict__ attn,
    const int*   __restrict__ epos,
    const float* __restrict__ hs_ner, const float* __restrict__ ts_ner,
    const float* __restrict__ Wh, const float* __restrict__ bh,
    const float* __restrict__ Wt, const float* __restrict__ bt,
    const float* __restrict__ Wb, const float* __restrict__ bb,
    float* __restrict__ out)
{
    extern __shared__ float sm[];
    const int tid = threadIdx.x;

    // ======== Phase 1: ht per-head partials (192) + LSE embeddings (16) ========
    for (int item = blockIdx.x; item < 208; item += NB_) {
        if (item < 192) {
            const int b = item / HEADS_, h = item % HEADS_;
            int s0[4], s1[4];
#pragma unroll
            for (int m = 0; m < 4; m++) {
                s0[m] = __ldg(&epos[b*8 + m])     + 1;
                s1[m] = __ldg(&epos[b*8 + 4 + m]) + 1;
            }
            const float* ah = attn + ((size_t)b*HEADS_ + h)*L_*L_;
#pragma unroll
            for (int r = 0; r < 2; r++) {
                const int l = tid + r*NT_;
                float a0 = 0.f, a1 = 0.f;
#pragma unroll
                for (int m = 0; m < 4; m++) {
                    a0 += __ldg(&ah[(size_t)s0[m]*L_ + l]);
                    a1 += __ldg(&ah[(size_t)s1[m]*L_ + l]);
                }
                g_htp[(b*HEADS_ + h)*L_ + l] = a0 * a1 * (1.0f/(16.0f*HEADS_));
            }
        } else {
            const int b = item - 192;
            int s0[4], s1[4];
#pragma unroll
            for (int m = 0; m < 4; m++) {
                s0[m] = __ldg(&epos[b*8 + m])     + 1;
                s1[m] = __ldg(&epos[b*8 + 4 + m]) + 1;
            }
            const float* seqb = seq + (size_t)b * L_ * HID_;
            for (int d = tid; d < HID_; d += NT_) {
                float v0[4], v1[4];
#pragma unroll
                for (int m = 0; m < 4; m++) {
                    v0[m] = __ldg(&seqb[(size_t)s0[m]*HID_ + d]);
                    v1[m] = __ldg(&seqb[(size_t)s1[m]*HID_ + d]);
                }
                float mx0 = fmaxf(fmaxf(v0[0],v0[1]), fmaxf(v0[2],v0[3]));
                float mx1 = fmaxf(fmaxf(v1[0],v1[1]), fmaxf(v1[2],v1[3]));
                float e0 = expf(v0[0]-mx0)+expf(v0[1]-mx0)+expf(v0[2]-mx0)+expf(v0[3]-mx0);
                float e1 = expf(v1[0]-mx1)+expf(v1[1]-mx1)+expf(v1[2]-mx1)+expf(v1[3]-mx1);
                g_hs[b*HID_ + d] = mx0 + logf(e0);
                g_ts[b*HID_ + d] = mx1 + logf(e1);
            }
        }
    }
    grid_barrier();

    // ======== Phase 2: rs chunk partials + sht chunk sums (256 items) ========
    {
        __shared__ float sht[32];
        for (int item = blockIdx.x; item < NCHUNK_*B_; item += NB_) {
            const int chunk = item / B_;
            const int b     = item % B_;
            __syncthreads();
            if (tid < 32) {
                const int l = chunk*32 + tid;
                float acc = 0.f;
#pragma unroll
                for (int h = 0; h < HEADS_; h++)
                    acc += g_htp[(b*HEADS_ + h)*L_ + l];
                sht[tid] = acc;
                float s = acc;
#pragma unroll
                for (int off = 16; off > 0; off >>= 1)
                    s += __shfl_down_sync(0xffffffffu, s, off);
                if (tid == 0) g_Sp[item] = s;
            }
            __syncthreads();
            const float* seqb = seq + ((size_t)b*L_ + chunk*32) * HID_;
            float a0 = 0.f, a1 = 0.f, a2 = 0.f;
#pragma unroll 8
            for (int l = 0; l < 32; l++) {
                const float w = sht[l];
                const float* row = seqb + (size_t)l * HID_;
                a0 = fmaf(__ldg(&row[tid       ]), w, a0);
                a1 = fmaf(__ldg(&row[tid + 256 ]), w, a1);
                a2 = fmaf(__ldg(&row[tid + 512 ]), w, a2);
            }
            float* dst = g_rsp + (size_t)item * HID_;
            dst[tid      ] = a0;
            dst[tid + 256] = a1;
            dst[tid + 512] = a2;
        }
    }
    grid_barrier();

    // ======== Phase 3: build g_x = [e | rs/(S+1e-5) | ner | pad0] ========
    for (int idx = blockIdx.x*NT_ + tid; idx < 2*B_*XS_; idx += NB_*NT_) {
        const int half = idx / (B_*XS_);
        const int rem  = idx % (B_*XS_);
        const int b    = rem / XS_;
        const int k    = rem % XS_;
        float v;
        if (k < HID_) {
            v = half ? g_ts[b*HID_ + k] : g_hs[b*HID_ + k];
        } else if (k < 2*HID_) {
            const int d = k - HID_;
            float acc = 0.f, S = 0.f;
#pragma unroll
            for (int c = 0; c < NCHUNK_; c++) {
                acc += g_rsp[((size_t)(c*B_ + b))*HID_ + d];
                S   += g_Sp[c*B_ + b];
            }
            v = acc / (S + 1e-5f);
        } else if (k < XDIM_) {
            const int d = k - 2*HID_;
            v = half ? __ldg(&ts_ner[b*NER_ + d]) : __ldg(&hs_ner[b*NER_ + d]);
        } else {
            v = 0.f;
        }
        g_x[idx] = v;
    }
    grid_barrier();

    // ======== Phase 4: hs2/ts2 = tanh(x @ W.T + b)  (192 tiles of 8 rows) ========
    {
        float* xsh = sm;               // B_ * XS_
        float* wsh = sm + B_*XS_;      // 8  * XS_
        for (int item = blockIdx.x; item < 192; item += NB_) {
            const int half  = item / 96;
            const int tile  = item % 96;
            const int obase = tile * 8;
            const float* Wsel = half ? Wt : Wh;
            const float* bias = half ? bt : bh;
            float*       outb = half ? g_ts2 : g_hs2;
            __syncthreads();
            // x fill (float4, L2 broadcast)
            const float* xsrc = g_x + (size_t)half * B_ * XS_;
            for (int i = tid*4; i < B_*XS_; i += NT_*4)
                *(float4*)&xsh[i] = *(const float4*)&xsrc[i];
            // W tile fill (coalesced)
            const float* Wbase = Wsel + (size_t)obase * XDIM_;
            for (int i = tid; i < 8*XDIM_; i += NT_) {
                const int r = i / XDIM_;
                const int k = i - r*XDIM_;
                wsh[r*XS_ + k] = __ldg(&Wbase[i]);
            }
            for (int i = tid; i < 8*(XS_-XDIM_); i += NT_) {
                const int r = i / (XS_-XDIM_);
                const int p = i - r*(XS_-XDIM_);
                wsh[r*XS_ + XDIM_ + p] = 0.f;
            }
            __syncthreads();

            const int w    = tid >> 5;
            const int lane = tid & 31;
            float acc[B_];
#pragma unroll
            for (int b = 0; b < B_; b++) acc[b] = 0.f;
            const float* wrow = wsh + w*XS_;
#pragma unroll 5
            for (int it = 0; it < 25; it++) {
                const int k = lane*2 + it*64;
                const float2 wv = *(const float2*)&wrow[k];
#pragma unroll
                for (int b = 0; b < B_; b++) {
                    const float2 xv = *(const float2*)&xsh[b*XS_ + k];
                    acc[b] = fmaf(wv.x, xv.x, acc[b]);
                    acc[b] = fmaf(wv.y, xv.y, acc[b]);
                }
            }
#pragma unroll
            for (int b = 0; b < B_; b++) {
#pragma unroll
                for (int off = 16; off > 0; off >>= 1)
                    acc[b] += __shfl_down_sync(0xffffffffu, acc[b], off);
            }
            if (lane == 0) {
                const int o = obase + w;
                const float bi = __ldg(&bias[o]);
#pragma unroll
                for (int b = 0; b < B_; b++)
                    outb[b*EMB_ + o] = tanhf(acc[b] + bi);
            }
        }
    }
    grid_barrier();

    // ======== Phase 5: logits (194 (class, batch-half) items) ========
    {
        float* hsh = sm;                 // 8*EMB_
        float* tsh = sm + 8*EMB_;        // 8*EMB_
        float* wsh = sm + 16*EMB_;       // EMB_*BLK_ = 6144
        float* red = sm + 16*EMB_ + EMB_*BLK_;  // 8 warps * 8
        for (int item = blockIdx.x; item < 2*NCLS_; item += NB_) {
            const int c  = item >> 1;
            const int bh = item & 1;
            __syncthreads();
            for (int i = tid; i < 8*EMB_; i += NT_) {
                hsh[i] = g_hs2[bh*8*EMB_ + i];
                tsh[i] = g_ts2[bh*8*EMB_ + i];
            }
            const float* Wc = Wb + (size_t)c * (EMB_*BLK_);
            for (int i = tid; i < EMB_*BLK_; i += NT_)
                wsh[i] = __ldg(&Wc[i]);
            __syncthreads();

            float acc[8];
#pragma unroll
            for (int b = 0; b < 8; b++) acc[b] = 0.f;
#pragma unroll
            for (int g = 0; g < 6; g++) {
                const int j = tid*4 + g*1024;
                const float4 wv = *(const float4*)&wsh[j];
                const int hidx  = j >> 3;
                const int tbase = ((j >> 6) << 3) | (j & 7);
#pragma unroll
                for (int b = 0; b < 8; b++) {
                    const float  hv = hsh[b*EMB_ + hidx];
                    const float4 tv = *(const float4*)&tsh[b*EMB_ + tbase];
                    acc[b] = fmaf(wv.x, hv*tv.x, acc[b]);
                    acc[b] = fmaf(wv.y, hv*tv.y, acc[b]);
                    acc[b] = fmaf(wv.z, hv*tv.z, acc[b]);
                    acc[b] = fmaf(wv.w, hv*tv.w, acc[b]);
                }
            }
            const int w = tid >> 5, lane = tid & 31;
#pragma unroll
            for (int b = 0; b < 8; b++) {
#pragma unroll
                for (int off = 16; off > 0; off >>= 1)
                    acc[b] += __shfl_down_sync(0xffffffffu, acc[b], off);
            }
            if (lane == 0) {
#pragma unroll
                for (int b = 0; b < 8; b++) red[w*8 + b] = acc[b];
            }
            __syncthreads();
            if (tid < 8) {
                float s = __ldg(&bb[c]);
#pragma unroll
                for (int w2 = 0; w2 < 8; w2++) s += red[w2*8 + tid];
                out[(bh*8 + tid)*NCLS_ + c] = s;
            }
        }
    }
}

// ---------------- launch ----------------
extern "C" void kernel_launch(void* const* d_in, const int* in_sizes, int n_in,
                              void* d_out, int out_size)
{
    const float* seq    = (const float*)d_in[0];
    const float* attn   = (const float*)d_in[1];
    const int*   epos   = (const int*)  d_in[2];
    const float* hs_ner = (const float*)d_in[3];
    const float* ts_ner = (const float*)d_in[4];
    const float* Wh     = (const float*)d_in[5];
    const float* bh     = (const float*)d_in[6];
    const float* Wt     = (const float*)d_in[7];
    const float* bt     = (const float*)d_in[8];
    const float* Wb     = (const float*)d_in[9];
    const float* bb     = (const float*)d_in[10];
    float* out = (float*)d_out;

    const int smem = (B_ + 8) * XS_ * 4;   // 153600 B (phase-4 max)
    cudaFuncSetAttribute(fused_kernel, cudaFuncAttributeMaxDynamicSharedMemorySize, smem);
    fused_kernel<<<NB_, NT_, smem>>>(seq, attn, epos, hs_ner, ts_ner,
                                     Wh, bh, Wt, bt, Wb, bb, out);
}

// round 6
// speedup vs baseline: 2.4441x; 1.4021x over previous
#include <cuda_runtime.h>
#include <math.h>

#define B_     16
#define L_     512
#define HID_   768
#define HEADS_ 12
#define EMB_   768
#define BLK_   8
#define NER_   6
#define NCLS_  97
#define XDIM_  1542            // 2*HID + NER
#define XP_    1792            // padded k stride (7 * 256)
#define NCHUNK_ 16
#define NB_    148
#define NT_    512

// ---------------- scratch ----------------
__device__ float g_htp[B_*HEADS_*L_];
__device__ float g_hs [B_*HID_];
__device__ float g_ts [B_*HID_];
__device__ float g_rsp[NCHUNK_*B_*HID_];
__device__ float g_Sp [NCHUNK_*B_];
__device__ float g_x  [2*B_*XP_];
__device__ float g_hs2[B_*EMB_];
__device__ float g_ts2[B_*EMB_];
__device__ unsigned long long g_bar = 0ULL;

__device__ __forceinline__ void grid_barrier() {
    __syncthreads();
    if (threadIdx.x == 0) {
        __threadfence();
        unsigned long long pos = atomicAdd(&g_bar, 1ULL);
        unsigned long long target = (pos / NB_ + 1ULL) * NB_;
        while (atomicAdd(&g_bar, 0ULL) < target) __nanosleep(64);
        __threadfence();
    }
    __syncthreads();
}

__global__ void __launch_bounds__(NT_, 1) fused_kernel(
    const float* __restrict__ seq,  const float* __restrict__ attn,
    const int*   __restrict__ epos,
    const float* __restrict__ hs_ner, const float* __restrict__ ts_ner,
    const float* __restrict__ Wh, const float* __restrict__ bh,
    const float* __restrict__ Wt, const float* __restrict__ bt,
    const float* __restrict__ Wb, const float* __restrict__ bb,
    float* __restrict__ out)
{
    extern __shared__ float sm[];
    const int tid = threadIdx.x;

    // ======== P1: ht per-head partials (flattened) + LSE embeddings ========
    {
        const int tot = B_*HEADS_*L_ + B_*HID_;   // 98304 + 12288
        for (int idx = blockIdx.x*NT_ + tid; idx < tot; idx += NB_*NT_) {
            if (idx < B_*HEADS_*L_) {
                const int l  = idx & (L_-1);
                const int bh = idx >> 9;           // b*HEADS_+h
                const int b  = bh / HEADS_;
                const float* ah = attn + (size_t)bh * L_ * L_;
                float a0 = 0.f, a1 = 0.f;
#pragma unroll
                for (int m = 0; m < 4; m++) {
                    const int s0 = __ldg(&epos[b*8 + m])     + 1;
                    const int s1 = __ldg(&epos[b*8 + 4 + m]) + 1;
                    a0 += __ldg(&ah[(size_t)s0*L_ + l]);
                    a1 += __ldg(&ah[(size_t)s1*L_ + l]);
                }
                g_htp[idx] = a0 * a1 * (1.0f/192.0f);
            } else {
                const int r = idx - B_*HEADS_*L_;
                const int b = r / HID_;
                const int d = r - b*HID_;
                const float* seqb = seq + (size_t)b * L_ * HID_;
                float v0[4], v1[4];
#pragma unroll
                for (int m = 0; m < 4; m++) {
                    const int s0 = __ldg(&epos[b*8 + m])     + 1;
                    const int s1 = __ldg(&epos[b*8 + 4 + m]) + 1;
                    v0[m] = __ldg(&seqb[(size_t)s0*HID_ + d]);
                    v1[m] = __ldg(&seqb[(size_t)s1*HID_ + d]);
                }
                float mx0 = fmaxf(fmaxf(v0[0],v0[1]), fmaxf(v0[2],v0[3]));
                float mx1 = fmaxf(fmaxf(v1[0],v1[1]), fmaxf(v1[2],v1[3]));
                float e0 = __expf(v0[0]-mx0)+__expf(v0[1]-mx0)+__expf(v0[2]-mx0)+__expf(v0[3]-mx0);
                float e1 = __expf(v1[0]-mx1)+__expf(v1[1]-mx1)+__expf(v1[2]-mx1)+__expf(v1[3]-mx1);
                g_hs[b*HID_ + d] = mx0 + __logf(e0);
                g_ts[b*HID_ + d] = mx1 + __logf(e1);
            }
        }
    }
    grid_barrier();

    // ======== P2: rs chunk partials (256 items, 2 l-subgroups x 256 d) ========
    {
        float* sht  = sm;          // 32
        float* pacc = sm + 32;     // 2*768
        const int lg = tid >> 8;          // 0..1 (16 l each)
        const int dt = tid & 255;
#pragma unroll 1
        for (int it2 = 0; it2 < 2; it2++) {
            const int item   = blockIdx.x + it2*NB_;
            const bool active = (item < NCHUNK_*B_);
            const int chunk = active ? item / B_ : 0;
            const int b     = active ? item % B_ : 0;
            __syncthreads();
            if (active && tid < 32) {
                const int l = chunk*32 + tid;
                float acc = 0.f;
#pragma unroll
                for (int h = 0; h < HEADS_; h++)
                    acc += g_htp[(b*HEADS_ + h)*L_ + l];
                sht[tid] = acc;
                float s = acc;
#pragma unroll
                for (int off = 16; off > 0; off >>= 1)
                    s += __shfl_down_sync(0xffffffffu, s, off);
                if (tid == 0) g_Sp[item] = s;
            }
            __syncthreads();
            if (active) {
                const float* seqb = seq + ((size_t)b*L_ + chunk*32 + lg*16) * HID_;
                float a0 = 0.f, a1 = 0.f, a2 = 0.f;
#pragma unroll 4
                for (int l = 0; l < 16; l++) {
                    const float w = sht[lg*16 + l];
                    const float* row = seqb + (size_t)l * HID_;
                    a0 = fmaf(__ldg(&row[dt      ]), w, a0);
                    a1 = fmaf(__ldg(&row[dt + 256]), w, a1);
                    a2 = fmaf(__ldg(&row[dt + 512]), w, a2);
                }
                pacc[lg*768 + dt      ] = a0;
                pacc[lg*768 + dt + 256] = a1;
                pacc[lg*768 + dt + 512] = a2;
            }
            __syncthreads();
            if (active) {
                float* dst = g_rsp + (size_t)item * HID_;
                for (int i = tid; i < HID_; i += NT_)        // strided: covers all 768
                    dst[i] = pacc[i] + pacc[768 + i];
            }
        }
    }
    grid_barrier();

    // ======== P3: build g_x = [e | rs/(S+1e-5) | ner | 0-pad] (stride XP_) ========
    for (int idx = blockIdx.x*NT_ + tid; idx < 2*B_*XP_; idx += NB_*NT_) {
        const int half = idx / (B_*XP_);
        const int rem  = idx - half*(B_*XP_);
        const int b    = rem / XP_;
        const int k    = rem - b*XP_;
        float v = 0.f;
        if (k < HID_) {
            v = half ? g_ts[b*HID_ + k] : g_hs[b*HID_ + k];
        } else if (k < 2*HID_) {
            const int d = k - HID_;
            float acc = 0.f, S = 0.f;
#pragma unroll
            for (int c = 0; c < NCHUNK_; c++) {
                acc += g_rsp[((size_t)(c*B_ + b))*HID_ + d];
                S   += g_Sp[c*B_ + b];
            }
            v = acc / (S + 1e-5f);
        } else if (k < XDIM_) {
            const int d = k - 2*HID_;
            v = half ? __ldg(&ts_ner[b*NER_ + d]) : __ldg(&hs_ner[b*NER_ + d]);
        }
        g_x[idx] = v;
    }
    grid_barrier();

    // ======== P4: hs2/ts2 = tanh(x @ W.T + b), register-tiled 4r x 8b ========
    {
        float* xsh  = sm;                  // B_*XP_ = 28672 floats
        float* red4 = sm + B_*XP_;         // 512 floats
#pragma unroll 1
        for (int it4 = 0; it4 < 2; it4++) {
            const int item   = blockIdx.x + it4*NB_;
            const bool active = (item < 192);
            const int half  = active ? item / 96 : 0;
            const int tile  = active ? item % 96 : 0;
            const int obase = tile * 8;
            const float* Wsel = half ? Wt : Wh;
            const float* bias = half ? bt : bh;
            float*       outb = half ? g_ts2 : g_hs2;
            __syncthreads();
            if (active) {
                const float* xsrc = g_x + (size_t)half * B_ * XP_;
                for (int i = tid*4; i < B_*XP_; i += NT_*4)
                    *(float4*)&xsh[i] = *(const float4*)&xsrc[i];
            }
            __syncthreads();
            if (active) {
                const int bh2 = tid >> 8;          // 0..1 -> 8 batches
                const int rh  = (tid >> 7) & 1;    // 0..1 -> 4 rows
                const int kt  = tid & 127;
                float acc[4][8];
#pragma unroll
                for (int r = 0; r < 4; r++)
#pragma unroll
                    for (int j = 0; j < 8; j++) acc[r][j] = 0.f;

                const float* xb = xsh + (size_t)(bh2*8) * XP_;
#pragma unroll
                for (int it = 0; it < 7; it++) {
                    const int k = kt*2 + it*256;
                    float2 wv[4];
#pragma unroll
                    for (int r = 0; r < 4; r++) {
                        const int o = obase + rh*4 + r;
                        wv[r] = (k < XDIM_)
                              ? *(const float2*)&Wsel[(size_t)o*XDIM_ + k]
                              : make_float2(0.f, 0.f);
                    }
#pragma unroll
                    for (int j = 0; j < 8; j++) {
                        const float2 xv = *(const float2*)&xb[j*XP_ + k];
#pragma unroll
                        for (int r = 0; r < 4; r++)
                            acc[r][j] = fmaf(wv[r].x, xv.x,
                                        fmaf(wv[r].y, xv.y, acc[r][j]));
                    }
                }
                // warp reduce over kt lanes
#pragma unroll
                for (int r = 0; r < 4; r++)
#pragma unroll
                    for (int j = 0; j < 8; j++)
#pragma unroll
                        for (int off = 16; off > 0; off >>= 1)
                            acc[r][j] += __shfl_down_sync(0xffffffffu, acc[r][j], off);
                if ((tid & 31) == 0) {
                    const int wq = (tid >> 5) & 3;
                    const int base = ((bh2*2 + rh)*4 + wq)*32;
#pragma unroll
                    for (int r = 0; r < 4; r++)
#pragma unroll
                        for (int j = 0; j < 8; j++)
                            red4[base + r*8 + j] = acc[r][j];
                }
            }
            __syncthreads();
            if (active && tid < 128) {
                const int ol = tid >> 4;       // 0..7
                const int b  = tid & 15;
                const int bh2 = b >> 3, j = b & 7;
                const int rh  = ol >> 2, r = ol & 3;
                float s = 0.f;
#pragma unroll
                for (int wq = 0; wq < 4; wq++)
                    s += red4[((bh2*2 + rh)*4 + wq)*32 + r*8 + j];
                const int o = obase + ol;
                outb[b*EMB_ + o] = tanhf(s + __ldg(&bias[o]));
            }
        }
    }
    grid_barrier();

    // ======== P5: logits (194 (class, batch-half) items) ========
    {
        float* hsh = sm;                   // 8*EMB_ = 6144
        float* tsh = sm + 6144;            // 6144
        float* wsh = sm + 12288;           // 6144
        float* red = sm + 18432;           // 16*8
#pragma unroll 1
        for (int it5 = 0; it5 < 2; it5++) {
            const int item   = blockIdx.x + it5*NB_;
            const bool active = (item < 2*NCLS_);
            const int c  = active ? (item >> 1) : 0;
            const int half = item & 1;
            __syncthreads();
            if (active) {
                const float* hsrc = g_hs2 + half*8*EMB_;
                const float* tsrc = g_ts2 + half*8*EMB_;
                const float* Wc   = Wb + (size_t)c * (EMB_*BLK_);
                for (int i = tid*4; i < 8*EMB_; i += NT_*4) {
                    *(float4*)&hsh[i] = *(const float4*)&hsrc[i];
                    *(float4*)&tsh[i] = *(const float4*)&tsrc[i];
                    *(float4*)&wsh[i] = *(const float4*)&Wc[i];
                }
            }
            __syncthreads();
            if (active) {
                float acc[8];
#pragma unroll
                for (int b = 0; b < 8; b++) acc[b] = 0.f;
#pragma unroll
                for (int g = 0; g < 3; g++) {
                    const int j = tid*4 + g*2048;
                    const float4 wv = *(const float4*)&wsh[j];
                    const int hidx  = j >> 3;
                    const int tbase = ((j >> 6) << 3) | (j & 7);
#pragma unroll
                    for (int b = 0; b < 8; b++) {
                        const float  hv = hsh[b*EMB_ + hidx];
                        const float4 tv = *(const float4*)&tsh[b*EMB_ + tbase];
                        acc[b] = fmaf(wv.x, hv*tv.x, acc[b]);
                        acc[b] = fmaf(wv.y, hv*tv.y, acc[b]);
                        acc[b] = fmaf(wv.z, hv*tv.z, acc[b]);
                        acc[b] = fmaf(wv.w, hv*tv.w, acc[b]);
                    }
                }
#pragma unroll
                for (int b = 0; b < 8; b++)
#pragma unroll
                    for (int off = 16; off > 0; off >>= 1)
                        acc[b] += __shfl_down_sync(0xffffffffu, acc[b], off);
                if ((tid & 31) == 0) {
                    const int w = tid >> 5;    // 0..15
#pragma unroll
                    for (int b = 0; b < 8; b++) red[w*8 + b] = acc[b];
                }
            }
            __syncthreads();
            if (active && tid < 8) {
                float s = __ldg(&bb[c]);
#pragma unroll
                for (int w2 = 0; w2 < 16; w2++) s += red[w2*8 + tid];
                out[(half*8 + tid)*NCLS_ + c] = s;
            }
        }
    }
}

// ---------------- launch ----------------
extern "C" void kernel_launch(void* const* d_in, const int* in_sizes, int n_in,
                              void* d_out, int out_size)
{
    const float* seq    = (const float*)d_in[0];
    const float* attn   = (const float*)d_in[1];
    const int*   epos   = (const int*)  d_in[2];
    const float* hs_ner = (const float*)d_in[3];
    const float* ts_ner = (const float*)d_in[4];
    const float* Wh     = (const float*)d_in[5];
    const float* bh     = (const float*)d_in[6];
    const float* Wt     = (const float*)d_in[7];
    const float* bt     = (const float*)d_in[8];
    const float* Wb     = (const float*)d_in[9];
    const float* bb     = (const float*)d_in[10];
    float* out = (float*)d_out;

    const int smem = (B_*XP_ + 512) * 4;   // 116736 B (P4 max)
    cudaFuncSetAttribute(fused_kernel, cudaFuncAttributeMaxDynamicSharedMemorySize, smem);
    fused_kernel<<<NB_, NT_, smem>>>(seq, attn, epos, hs_ner, ts_ner,
                                     Wh, bh, Wt, bt, Wb, bb, out);
}

// round 7
// speedup vs baseline: 2.6072x; 1.0667x over previous
#include <cuda_runtime.h>
#include <math.h>

#define B_     16
#define L_     512
#define HID_   768
#define HEADS_ 12
#define EMB_   768
#define BLK_   8
#define NER_   6
#define NCLS_  97
#define XDIM_  1542            // 2*HID + NER
#define XP_    1792            // padded k stride (14 * 128)
#define NCHUNK_ 16
#define NT_    512

// ---------------- scratch ----------------
__device__ float g_htp[B_*HEADS_*L_];
__device__ float g_hs [B_*HID_];
__device__ float g_ts [B_*HID_];
__device__ float g_rsp[NCHUNK_*B_*HID_];
__device__ float g_Sp [NCHUNK_*B_];
__device__ float g_x  [2*B_*XP_];
__device__ float g_hs2[B_*EMB_];
__device__ float g_ts2[B_*EMB_];
__device__ unsigned long long g_bar = 0ULL;

__device__ __forceinline__ void grid_barrier() {
    __syncthreads();
    if (threadIdx.x == 0) {
        __threadfence();
        unsigned long long nb = gridDim.x;
        unsigned long long pos = atomicAdd(&g_bar, 1ULL);
        unsigned long long target = (pos / nb + 1ULL) * nb;
        while (atomicAdd(&g_bar, 0ULL) < target) __nanosleep(64);
        __threadfence();
    }
    __syncthreads();
}

__global__ void __launch_bounds__(NT_, 2) fused_kernel(
    const float* __restrict__ seq,  const float* __restrict__ attn,
    const int*   __restrict__ epos,
    const float* __restrict__ hs_ner, const float* __restrict__ ts_ner,
    const float* __restrict__ Wh, const float* __restrict__ bh,
    const float* __restrict__ Wt, const float* __restrict__ bt,
    const float* __restrict__ Wb, const float* __restrict__ bb,
    float* __restrict__ out)
{
    extern __shared__ float sm[];
    const int tid = threadIdx.x;
    const int nb  = gridDim.x;

    // ======== P1: ht per-head partials (flattened) + LSE embeddings ========
    {
        const int tot = B_*HEADS_*L_ + B_*HID_;   // 98304 + 12288
        for (int idx = blockIdx.x*NT_ + tid; idx < tot; idx += nb*NT_) {
            if (idx < B_*HEADS_*L_) {
                const int l  = idx & (L_-1);
                const int bh = idx >> 9;           // b*HEADS_+h
                const int b  = bh / HEADS_;
                const float* ah = attn + (size_t)bh * L_ * L_;
                float a0 = 0.f, a1 = 0.f;
#pragma unroll
                for (int m = 0; m < 4; m++) {
                    const int s0 = __ldg(&epos[b*8 + m])     + 1;
                    const int s1 = __ldg(&epos[b*8 + 4 + m]) + 1;
                    a0 += __ldg(&ah[(size_t)s0*L_ + l]);
                    a1 += __ldg(&ah[(size_t)s1*L_ + l]);
                }
                g_htp[idx] = a0 * a1 * (1.0f/192.0f);
            } else {
                const int r = idx - B_*HEADS_*L_;
                const int b = r / HID_;
                const int d = r - b*HID_;
                const float* seqb = seq + (size_t)b * L_ * HID_;
                float v0[4], v1[4];
#pragma unroll
                for (int m = 0; m < 4; m++) {
                    const int s0 = __ldg(&epos[b*8 + m])     + 1;
                    const int s1 = __ldg(&epos[b*8 + 4 + m]) + 1;
                    v0[m] = __ldg(&seqb[(size_t)s0*HID_ + d]);
                    v1[m] = __ldg(&seqb[(size_t)s1*HID_ + d]);
                }
                float mx0 = fmaxf(fmaxf(v0[0],v0[1]), fmaxf(v0[2],v0[3]));
                float mx1 = fmaxf(fmaxf(v1[0],v1[1]), fmaxf(v1[2],v1[3]));
                float e0 = __expf(v0[0]-mx0)+__expf(v0[1]-mx0)+__expf(v0[2]-mx0)+__expf(v0[3]-mx0);
                float e1 = __expf(v1[0]-mx1)+__expf(v1[1]-mx1)+__expf(v1[2]-mx1)+__expf(v1[3]-mx1);
                g_hs[b*HID_ + d] = mx0 + __logf(e0);
                g_ts[b*HID_ + d] = mx1 + __logf(e1);
            }
        }
    }
    grid_barrier();

    // ======== P2: rs chunk partials (256 items, grid-stride) ========
    {
        float* sht  = sm;          // 32
        float* pacc = sm + 32;     // 2*768
        const int lg = tid >> 8;          // 0..1 (16 l each)
        const int dt = tid & 255;
        for (int item = blockIdx.x; item < NCHUNK_*B_; item += nb) {
            const int chunk = item / B_;
            const int b     = item % B_;
            __syncthreads();
            if (tid < 32) {
                const int l = chunk*32 + tid;
                float acc = 0.f;
#pragma unroll
                for (int h = 0; h < HEADS_; h++)
                    acc += g_htp[(b*HEADS_ + h)*L_ + l];
                sht[tid] = acc;
                float s = acc;
#pragma unroll
                for (int off = 16; off > 0; off >>= 1)
                    s += __shfl_down_sync(0xffffffffu, s, off);
                if (tid == 0) g_Sp[item] = s;
            }
            __syncthreads();
            {
                const float* seqb = seq + ((size_t)b*L_ + chunk*32 + lg*16) * HID_;
                float a0 = 0.f, a1 = 0.f, a2 = 0.f;
#pragma unroll 4
                for (int l = 0; l < 16; l++) {
                    const float w = sht[lg*16 + l];
                    const float* row = seqb + (size_t)l * HID_;
                    a0 = fmaf(__ldg(&row[dt      ]), w, a0);
                    a1 = fmaf(__ldg(&row[dt + 256]), w, a1);
                    a2 = fmaf(__ldg(&row[dt + 512]), w, a2);
                }
                pacc[lg*768 + dt      ] = a0;
                pacc[lg*768 + dt + 256] = a1;
                pacc[lg*768 + dt + 512] = a2;
            }
            __syncthreads();
            {
                float* dst = g_rsp + (size_t)item * HID_;
                for (int i = tid; i < HID_; i += NT_)
                    dst[i] = pacc[i] + pacc[768 + i];
            }
        }
    }
    grid_barrier();

    // ======== P3: build g_x = [e | rs/(S+1e-5) | ner | 0-pad] ========
    for (int idx = blockIdx.x*NT_ + tid; idx < 2*B_*XP_; idx += nb*NT_) {
        const int half = idx / (B_*XP_);
        const int rem  = idx - half*(B_*XP_);
        const int b    = rem / XP_;
        const int k    = rem - b*XP_;
        float v = 0.f;
        if (k < HID_) {
            v = half ? g_ts[b*HID_ + k] : g_hs[b*HID_ + k];
        } else if (k < 2*HID_) {
            const int d = k - HID_;
            float acc = 0.f, S = 0.f;
#pragma unroll
            for (int c = 0; c < NCHUNK_; c++) {
                acc += g_rsp[((size_t)(c*B_ + b))*HID_ + d];
                S   += g_Sp[c*B_ + b];
            }
            v = acc / (S + 1e-5f);
        } else if (k < XDIM_) {
            const int d = k - 2*HID_;
            v = half ? __ldg(&ts_ner[b*NER_ + d]) : __ldg(&hs_ner[b*NER_ + d]);
        }
        g_x[idx] = v;
    }
    grid_barrier();

    // ======== P4: hs2/ts2 = tanh(x @ W.T + b) ========
    // 384 items: (half, tile, batch-group). Each item: 8 rows x 8 batches.
    // Thread tile: 2 rows x 4 batches; kt (64 lanes = 2 warps) over k.
    {
        float* xsh = sm;                // 8 * XP_ = 14336 floats
        float* red = sm + 8*XP_;        // 16 warps * 8
        for (int item = blockIdx.x; item < 384; item += nb) {
            const int bg     = item & 1;
            const int tile_h = item >> 1;       // 0..191
            const int half   = tile_h / 96;
            const int tile   = tile_h % 96;
            const int obase  = tile * 8;
            const float* Wsel = half ? Wt : Wh;
            const float* bias = half ? bt : bh;
            float*       outb = half ? g_ts2 : g_hs2;
            __syncthreads();
            {   // stage 8 batches of x (includes zero pad)
                const float* xsrc = g_x + ((size_t)half*B_ + bg*8) * XP_;
                for (int i = tid*4; i < 8*XP_; i += NT_*4)
                    *(float4*)&xsh[i] = *(const float4*)&xsrc[i];
            }
            __syncthreads();
            {
                const int g  = tid >> 6;        // 0..7
                const int kt = tid & 63;        // 0..63
                const int rh = g >> 1;          // 0..3 -> rows rh*2, rh*2+1
                const int bq = g & 1;           // 0..1 -> batches bq*4..bq*4+3
                const int o0 = obase + rh*2;

                float acc[2][4];
#pragma unroll
                for (int r = 0; r < 2; r++)
#pragma unroll
                    for (int j = 0; j < 4; j++) acc[r][j] = 0.f;

                const float* xb = xsh + (size_t)(bq*4) * XP_;
                const float* W0 = Wsel + (size_t)o0     * XDIM_;
                const float* W1 = Wsel + (size_t)(o0+1) * XDIM_;
#pragma unroll
                for (int it = 0; it < 14; it++) {
                    const int k = kt*2 + it*128;
                    float2 wv0 = make_float2(0.f, 0.f);
                    float2 wv1 = make_float2(0.f, 0.f);
                    if (k < XDIM_) {
                        wv0 = *(const float2*)&W0[k];
                        wv1 = *(const float2*)&W1[k];
                    }
#pragma unroll
                    for (int j = 0; j < 4; j++) {
                        const float2 xv = *(const float2*)&xb[j*XP_ + k];
                        acc[0][j] = fmaf(wv0.x, xv.x, fmaf(wv0.y, xv.y, acc[0][j]));
                        acc[1][j] = fmaf(wv1.x, xv.x, fmaf(wv1.y, xv.y, acc[1][j]));
                    }
                }
#pragma unroll
                for (int r = 0; r < 2; r++)
#pragma unroll
                    for (int j = 0; j < 4; j++)
#pragma unroll
                        for (int off = 16; off > 0; off >>= 1)
                            acc[r][j] += __shfl_down_sync(0xffffffffu, acc[r][j], off);
                if ((tid & 31) == 0) {
                    const int w = tid >> 5;     // 0..15  (= g*2 + sub)
#pragma unroll
                    for (int r = 0; r < 2; r++)
#pragma unroll
                        for (int j = 0; j < 4; j++)
                            red[w*8 + r*4 + j] = acc[r][j];
                }
            }
            __syncthreads();
            if (tid < 64) {
                const int ro = tid >> 3;       // 0..7 local row
                const int j  = tid & 7;        // 0..7 local batch
                const int rh = ro >> 1, rr = ro & 1;
                const int bq = j >> 2,  jj = j & 3;
                const int g  = rh*2 + bq;
                const float s = red[(2*g  )*8 + rr*4 + jj]
                              + red[(2*g+1)*8 + rr*4 + jj];
                const int o = obase + rh*2 + rr;
                outb[(bg*8 + j)*EMB_ + o] = tanhf(s + __ldg(&bias[o]));
            }
        }
    }
    grid_barrier();

    // ======== P5: logits (194 (class, batch-half) items) ========
    {
        float* hsh = sm;                   // 6144
        float* tsh = sm + 6144;            // 6144
        float* wsh = sm + 12288;           // 6144
        float* red = sm + 18432;           // 16*8
        for (int item = blockIdx.x; item < 2*NCLS_; item += nb) {
            const int c    = item >> 1;
            const int half = item & 1;
            __syncthreads();
            {
                const float* hsrc = g_hs2 + half*8*EMB_;
                const float* tsrc = g_ts2 + half*8*EMB_;
                const float* Wc   = Wb + (size_t)c * (EMB_*BLK_);
                for (int i = tid*4; i < 8*EMB_; i += NT_*4) {
                    *(float4*)&hsh[i] = *(const float4*)&hsrc[i];
                    *(float4*)&tsh[i] = *(const float4*)&tsrc[i];
                    *(float4*)&wsh[i] = *(const float4*)&Wc[i];
                }
            }
            __syncthreads();
            {
                float acc[8];
#pragma unroll
                for (int b = 0; b < 8; b++) acc[b] = 0.f;
#pragma unroll
                for (int g = 0; g < 3; g++) {
                    const int j = tid*4 + g*2048;
                    const float4 wv = *(const float4*)&wsh[j];
                    const int hidx  = j >> 3;
                    const int tbase = ((j >> 6) << 3) | (j & 7);
#pragma unroll
                    for (int b = 0; b < 8; b++) {
                        const float  hv = hsh[b*EMB_ + hidx];
                        const float4 tv = *(const float4*)&tsh[b*EMB_ + tbase];
                        acc[b] = fmaf(wv.x, hv*tv.x, acc[b]);
                        acc[b] = fmaf(wv.y, hv*tv.y, acc[b]);
                        acc[b] = fmaf(wv.z, hv*tv.z, acc[b]);
                        acc[b] = fmaf(wv.w, hv*tv.w, acc[b]);
                    }
                }
#pragma unroll
                for (int b = 0; b < 8; b++)
#pragma unroll
                    for (int off = 16; off > 0; off >>= 1)
                        acc[b] += __shfl_down_sync(0xffffffffu, acc[b], off);
                if ((tid & 31) == 0) {
                    const int w = tid >> 5;    // 0..15
#pragma unroll
                    for (int b = 0; b < 8; b++) red[w*8 + b] = acc[b];
                }
            }
            __syncthreads();
            if (tid < 8) {
                float s = __ldg(&bb[c]);
#pragma unroll
                for (int w2 = 0; w2 < 16; w2++) s += red[w2*8 + tid];
                out[(half*8 + tid)*NCLS_ + c] = s;
            }
        }
    }
}

// ---------------- launch ----------------
extern "C" void kernel_launch(void* const* d_in, const int* in_sizes, int n_in,
                              void* d_out, int out_size)
{
    const float* seq    = (const float*)d_in[0];
    const float* attn   = (const float*)d_in[1];
    const int*   epos   = (const int*)  d_in[2];
    const float* hs_ner = (const float*)d_in[3];
    const float* ts_ner = (const float*)d_in[4];
    const float* Wh     = (const float*)d_in[5];
    const float* bh     = (const float*)d_in[6];
    const float* Wt     = (const float*)d_in[7];
    const float* bt     = (const float*)d_in[8];
    const float* Wb     = (const float*)d_in[9];
    const float* bb     = (const float*)d_in[10];
    float* out = (float*)d_out;

    const int smem = (18432 + 128) * 4;    // 74240 B (P5 max; P4 = 57856 B)
    cudaFuncSetAttribute(fused_kernel, cudaFuncAttributeMaxDynamicSharedMemorySize, smem);

    int nsm = 148;
    cudaDeviceGetAttribute(&nsm, cudaDevAttrMultiProcessorCount, 0);
    int bpm = 1;
    cudaOccupancyMaxActiveBlocksPerMultiprocessor(&bpm, fused_kernel, NT_, smem);
    if (bpm < 1) bpm = 1;
    const int nb = nsm * bpm;   // all CTAs co-resident => grid barrier is safe

    fused_kernel<<<nb, NT_, smem>>>(seq, attn, epos, hs_ner, ts_ner,
                                    Wh, bh, Wt, bt, Wb, bb, out);
}

// round 8
// speedup vs baseline: 2.6129x; 1.0022x over previous
#include <cuda_runtime.h>
#include <math.h>

#define B_     16
#define L_     512
#define HID_   768
#define HEADS_ 12
#define EMB_   768
#define BLK_   8
#define NER_   6
#define NCLS_  97
#define XDIM_  1542            // 2*HID + NER
#define XP_    1792            // padded k stride (14 * 128)
#define NCHUNK_ 16
#define NT_    512

// ---------------- scratch ----------------
__device__ float g_htp[B_*HEADS_*L_];
__device__ float g_hs [B_*HID_];
__device__ float g_ts [B_*HID_];
__device__ float g_rsp[NCHUNK_*B_*HID_];
__device__ float g_Sp [NCHUNK_*B_];
__device__ float g_x  [2*B_*XP_];
__device__ float g_hs2[B_*EMB_];
__device__ float g_ts2[B_*EMB_];
__device__ unsigned long long g_bar = 0ULL;

__device__ __forceinline__ void grid_barrier() {
    __syncthreads();
    if (threadIdx.x == 0) {
        __threadfence();
        unsigned long long nb = gridDim.x;
        unsigned long long pos = atomicAdd(&g_bar, 1ULL);
        unsigned long long target = (pos / nb + 1ULL) * nb;
        while (atomicAdd(&g_bar, 0ULL) < target) __nanosleep(64);
        __threadfence();
    }
    __syncthreads();
}

__device__ __forceinline__ void l2_prefetch(const void* p) {
    asm volatile("prefetch.global.L2 [%0];" :: "l"(p));
}

__global__ void __launch_bounds__(NT_, 2) fused_kernel(
    const float* __restrict__ seq,  const float* __restrict__ attn,
    const int*   __restrict__ epos,
    const float* __restrict__ hs_ner, const float* __restrict__ ts_ner,
    const float* __restrict__ Wh, const float* __restrict__ bh,
    const float* __restrict__ Wt, const float* __restrict__ bt,
    const float* __restrict__ Wb, const float* __restrict__ bb,
    float* __restrict__ out)
{
    extern __shared__ float sm[];
    const int tid = threadIdx.x;
    const int nb  = gridDim.x;

    // ======== P0: warm L2 with the weight streams (overlaps P1/P2) ========
    {
        const int gt  = blockIdx.x*NT_ + tid;
        const int gn  = nb*NT_;
        const size_t wsz = (size_t)EMB_*XDIM_;                 // 1.18M floats
        for (size_t i = (size_t)gt*32; i < wsz; i += (size_t)gn*32) {
            l2_prefetch(Wh + i);
            l2_prefetch(Wt + i);
        }
        const size_t bsz = (size_t)NCLS_*EMB_*BLK_;
        for (size_t i = (size_t)gt*32; i < bsz; i += (size_t)gn*32)
            l2_prefetch(Wb + i);
    }

    // ======== P1: ht per-head partials (flattened) + LSE embeddings ========
    {
        const int tot = B_*HEADS_*L_ + B_*HID_;   // 98304 + 12288
        for (int idx = blockIdx.x*NT_ + tid; idx < tot; idx += nb*NT_) {
            if (idx < B_*HEADS_*L_) {
                const int l  = idx & (L_-1);
                const int bh = idx >> 9;           // b*HEADS_+h
                const int b  = bh / HEADS_;
                const float* ah = attn + (size_t)bh * L_ * L_;
                float a0 = 0.f, a1 = 0.f;
#pragma unroll
                for (int m = 0; m < 4; m++) {
                    const int s0 = __ldg(&epos[b*8 + m])     + 1;
                    const int s1 = __ldg(&epos[b*8 + 4 + m]) + 1;
                    a0 += __ldg(&ah[(size_t)s0*L_ + l]);
                    a1 += __ldg(&ah[(size_t)s1*L_ + l]);
                }
                g_htp[idx] = a0 * a1 * (1.0f/192.0f);
            } else {
                const int r = idx - B_*HEADS_*L_;
                const int b = r / HID_;
                const int d = r - b*HID_;
                const float* seqb = seq + (size_t)b * L_ * HID_;
                float v0[4], v1[4];
#pragma unroll
                for (int m = 0; m < 4; m++) {
                    const int s0 = __ldg(&epos[b*8 + m])     + 1;
                    const int s1 = __ldg(&epos[b*8 + 4 + m]) + 1;
                    v0[m] = __ldg(&seqb[(size_t)s0*HID_ + d]);
                    v1[m] = __ldg(&seqb[(size_t)s1*HID_ + d]);
                }
                float mx0 = fmaxf(fmaxf(v0[0],v0[1]), fmaxf(v0[2],v0[3]));
                float mx1 = fmaxf(fmaxf(v1[0],v1[1]), fmaxf(v1[2],v1[3]));
                float e0 = __expf(v0[0]-mx0)+__expf(v0[1]-mx0)+__expf(v0[2]-mx0)+__expf(v0[3]-mx0);
                float e1 = __expf(v1[0]-mx1)+__expf(v1[1]-mx1)+__expf(v1[2]-mx1)+__expf(v1[3]-mx1);
                g_hs[b*HID_ + d] = mx0 + __logf(e0);
                g_ts[b*HID_ + d] = mx1 + __logf(e1);
            }
        }
    }
    grid_barrier();

    // ======== P2: rs chunk partials (256 items, float2, 4 l-subgroups) ========
    {
        float* sht  = sm;          // 32
        float* pacc = sm + 32;     // 4*768
        const int lg = tid >> 7;          // 0..3 (8 l each)
        const int dt = tid & 127;         // float2 column
        for (int item = blockIdx.x; item < NCHUNK_*B_; item += nb) {
            const int chunk = item / B_;
            const int b     = item % B_;
            __syncthreads();
            if (tid < 32) {
                const int l = chunk*32 + tid;
                float acc = 0.f;
#pragma unroll
                for (int h = 0; h < HEADS_; h++)
                    acc += g_htp[(b*HEADS_ + h)*L_ + l];
                sht[tid] = acc;
                float s = acc;
#pragma unroll
                for (int off = 16; off > 0; off >>= 1)
                    s += __shfl_down_sync(0xffffffffu, s, off);
                if (tid == 0) g_Sp[item] = s;
            }
            __syncthreads();
            {
                const float* seqb = seq + ((size_t)b*L_ + chunk*32 + lg*8) * HID_;
                float2 a0 = {0.f,0.f}, a1 = {0.f,0.f}, a2 = {0.f,0.f};
#pragma unroll
                for (int l = 0; l < 8; l++) {
                    const float w = sht[lg*8 + l];
                    const float* row = seqb + (size_t)l * HID_;
                    const float2 v0 = *(const float2*)&row[dt*2      ];
                    const float2 v1 = *(const float2*)&row[dt*2 + 256];
                    const float2 v2 = *(const float2*)&row[dt*2 + 512];
                    a0.x = fmaf(v0.x, w, a0.x); a0.y = fmaf(v0.y, w, a0.y);
                    a1.x = fmaf(v1.x, w, a1.x); a1.y = fmaf(v1.y, w, a1.y);
                    a2.x = fmaf(v2.x, w, a2.x); a2.y = fmaf(v2.y, w, a2.y);
                }
                float* pp = pacc + lg*768;
                *(float2*)&pp[dt*2      ] = a0;
                *(float2*)&pp[dt*2 + 256] = a1;
                *(float2*)&pp[dt*2 + 512] = a2;
            }
            __syncthreads();
            {
                float* dst = g_rsp + (size_t)item * HID_;
                for (int i = tid; i < HID_; i += NT_)
                    dst[i] = (pacc[i] + pacc[768 + i])
                           + (pacc[1536 + i] + pacc[2304 + i]);
            }
        }
    }
    grid_barrier();

    // ======== P3: build g_x = [e | rs/(S+1e-5) | ner | 0-pad] ========
    for (int idx = blockIdx.x*NT_ + tid; idx < 2*B_*XP_; idx += nb*NT_) {
        const int half = idx / (B_*XP_);
        const int rem  = idx - half*(B_*XP_);
        const int b    = rem / XP_;
        const int k    = rem - b*XP_;
        float v = 0.f;
        if (k < HID_) {
            v = half ? g_ts[b*HID_ + k] : g_hs[b*HID_ + k];
        } else if (k < 2*HID_) {
            const int d = k - HID_;
            float acc = 0.f, S = 0.f;
#pragma unroll
            for (int c = 0; c < NCHUNK_; c++) {
                acc += g_rsp[((size_t)(c*B_ + b))*HID_ + d];
                S   += g_Sp[c*B_ + b];
            }
            v = acc / (S + 1e-5f);
        } else if (k < XDIM_) {
            const int d = k - 2*HID_;
            v = half ? __ldg(&ts_ner[b*NER_ + d]) : __ldg(&hs_ner[b*NER_ + d]);
        }
        g_x[idx] = v;
    }
    grid_barrier();

    // ======== P4: hs2/ts2 = tanh(x @ W.T + b) ========
    // 384 items: (half, tile, batch-group). Each item: 8 rows x 8 batches.
    {
        float* xsh = sm;                // 8 * XP_ = 14336 floats
        float* red = sm + 8*XP_;        // 16 warps * 8
        for (int item = blockIdx.x; item < 384; item += nb) {
            const int bg     = item & 1;
            const int tile_h = item >> 1;       // 0..191
            const int half   = tile_h / 96;
            const int tile   = tile_h % 96;
            const int obase  = tile * 8;
            const float* Wsel = half ? Wt : Wh;
            const float* bias = half ? bt : bh;
            float*       outb = half ? g_ts2 : g_hs2;
            __syncthreads();
            {   // stage 8 batches of x (includes zero pad)
                const float* xsrc = g_x + ((size_t)half*B_ + bg*8) * XP_;
                for (int i = tid*4; i < 8*XP_; i += NT_*4)
                    *(float4*)&xsh[i] = *(const float4*)&xsrc[i];
            }
            __syncthreads();
            {
                const int g  = tid >> 6;        // 0..7
                const int kt = tid & 63;        // 0..63
                const int rh = g >> 1;          // 0..3 -> rows rh*2, rh*2+1
                const int bq = g & 1;           // 0..1 -> batches bq*4..bq*4+3
                const int o0 = obase + rh*2;

                float acc[2][4];
#pragma unroll
                for (int r = 0; r < 2; r++)
#pragma unroll
                    for (int j = 0; j < 4; j++) acc[r][j] = 0.f;

                const float* xb = xsh + (size_t)(bq*4) * XP_;
                const float* W0 = Wsel + (size_t)o0     * XDIM_;
                const float* W1 = Wsel + (size_t)(o0+1) * XDIM_;
#pragma unroll
                for (int it = 0; it < 14; it++) {
                    const int k = kt*2 + it*128;
                    float2 wv0 = make_float2(0.f, 0.f);
                    float2 wv1 = make_float2(0.f, 0.f);
                    if (k < XDIM_) {
                        wv0 = *(const float2*)&W0[k];
                        wv1 = *(const float2*)&W1[k];
                    }
#pragma unroll
                    for (int j = 0; j < 4; j++) {
                        const float2 xv = *(const float2*)&xb[j*XP_ + k];
                        acc[0][j] = fmaf(wv0.x, xv.x, fmaf(wv0.y, xv.y, acc[0][j]));
                        acc[1][j] = fmaf(wv1.x, xv.x, fmaf(wv1.y, xv.y, acc[1][j]));
                    }
                }
#pragma unroll
                for (int r = 0; r < 2; r++)
#pragma unroll
                    for (int j = 0; j < 4; j++)
#pragma unroll
                        for (int off = 16; off > 0; off >>= 1)
                            acc[r][j] += __shfl_down_sync(0xffffffffu, acc[r][j], off);
                if ((tid & 31) == 0) {
                    const int w = tid >> 5;     // 0..15  (= g*2 + sub)
#pragma unroll
                    for (int r = 0; r < 2; r++)
#pragma unroll
                        for (int j = 0; j < 4; j++)
                            red[w*8 + r*4 + j] = acc[r][j];
                }
            }
            __syncthreads();
            if (tid < 64) {
                const int ro = tid >> 3;       // 0..7 local row
                const int j  = tid & 7;        // 0..7 local batch
                const int rh = ro >> 1, rr = ro & 1;
                const int bq = j >> 2,  jj = j & 3;
                const int g  = rh*2 + bq;
                const float s = red[(2*g  )*8 + rr*4 + jj]
                              + red[(2*g+1)*8 + rr*4 + jj];
                const int o = obase + rh*2 + rr;
                outb[(bg*8 + j)*EMB_ + o] = tanhf(s + __ldg(&bias[o]));
            }
        }
    }
    grid_barrier();

    // ======== P5: logits (194 (class, batch-half) items) ========
    {
        float* hsh = sm;                   // 6144
        float* tsh = sm + 6144;            // 6144
        float* wsh = sm + 12288;           // 6144
        float* red = sm + 18432;           // 16*8
        for (int item = blockIdx.x; item < 2*NCLS_; item += nb) {
            const int c    = item >> 1;
            const int half = item & 1;
            __syncthreads();
            {
                const float* hsrc = g_hs2 + half*8*EMB_;
                const float* tsrc = g_ts2 + half*8*EMB_;
                const float* Wc   = Wb + (size_t)c * (EMB_*BLK_);
                for (int i = tid*4; i < 8*EMB_; i += NT_*4) {
                    *(float4*)&hsh[i] = *(const float4*)&hsrc[i];
                    *(float4*)&tsh[i] = *(const float4*)&tsrc[i];
                    *(float4*)&wsh[i] = *(const float4*)&Wc[i];
                }
            }
            __syncthreads();
            {
                float acc[8];
#pragma unroll
                for (int b = 0; b < 8; b++) acc[b] = 0.f;
#pragma unroll
                for (int g = 0; g < 3; g++) {
                    const int j = tid*4 + g*2048;
                    const float4 wv = *(const float4*)&wsh[j];
                    const int hidx  = j >> 3;
                    const int tbase = ((j >> 6) << 3) | (j & 7);
#pragma unroll
                    for (int b = 0; b < 8; b++) {
                        const float  hv = hsh[b*EMB_ + hidx];
                        const float4 tv = *(const float4*)&tsh[b*EMB_ + tbase];
                        acc[b] = fmaf(wv.x, hv*tv.x, acc[b]);
                        acc[b] = fmaf(wv.y, hv*tv.y, acc[b]);
                        acc[b] = fmaf(wv.z, hv*tv.z, acc[b]);
                        acc[b] = fmaf(wv.w, hv*tv.w, acc[b]);
                    }
                }
#pragma unroll
                for (int b = 0; b < 8; b++)
#pragma unroll
                    for (int off = 16; off > 0; off >>= 1)
                        acc[b] += __shfl_down_sync(0xffffffffu, acc[b], off);
                if ((tid & 31) == 0) {
                    const int w = tid >> 5;    // 0..15
#pragma unroll
                    for (int b = 0; b < 8; b++) red[w*8 + b] = acc[b];
                }
            }
            __syncthreads();
            if (tid < 8) {
                float s = __ldg(&bb[c]);
#pragma unroll
                for (int w2 = 0; w2 < 16; w2++) s += red[w2*8 + tid];
                out[(half*8 + tid)*NCLS_ + c] = s;
            }
        }
    }
}

// ---------------- launch ----------------
extern "C" void kernel_launch(void* const* d_in, const int* in_sizes, int n_in,
                              void* d_out, int out_size)
{
    const float* seq    = (const float*)d_in[0];
    const float* attn   = (const float*)d_in[1];
    const int*   epos   = (const int*)  d_in[2];
    const float* hs_ner = (const float*)d_in[3];
    const float* ts_ner = (const float*)d_in[4];
    const float* Wh     = (const float*)d_in[5];
    const float* bh     = (const float*)d_in[6];
    const float* Wt     = (const float*)d_in[7];
    const float* bt     = (const float*)d_in[8];
    const float* Wb     = (const float*)d_in[9];
    const float* bb     = (const float*)d_in[10];
    float* out = (float*)d_out;

    const int smem = (18432 + 128) * 4;    // 74240 B (P5 max)
    cudaFuncSetAttribute(fused_kernel, cudaFuncAttributeMaxDynamicSharedMemorySize, smem);

    int nsm = 148;
    cudaDeviceGetAttribute(&nsm, cudaDevAttrMultiProcessorCount, 0);
    int bpm = 1;
    cudaOccupancyMaxActiveBlocksPerMultiprocessor(&bpm, fused_kernel, NT_, smem);
    if (bpm < 1) bpm = 1;
    const int nb = nsm * bpm;   // all CTAs co-resident => grid barrier safe

    fused_kernel<<<nb, NT_, smem>>>(seq, attn, epos, hs_ner, ts_ner,
                                    Wh, bh, Wt, bt, Wb, bb, out);
}

// round 9
// speedup vs baseline: 2.6866x; 1.0282x over previous
#include <cuda_runtime.h>
#include <math.h>

#define B_     16
#define L_     512
#define HID_   768
#define HEADS_ 12
#define EMB_   768
#define BLK_   8
#define NER_   6
#define NCLS_  97
#define XDIM_  1542            // 2*HID + NER
#define XP_    1792            // padded k stride (14 * 128)
#define NCHUNK_ 16
#define NT_    512

// ---------------- scratch ----------------
__device__ float g_htp[B_*HEADS_*L_];
__device__ float g_hs [B_*HID_];
__device__ float g_ts [B_*HID_];
__device__ float g_rsp[NCHUNK_*B_*HID_];
__device__ float g_Sp [NCHUNK_*B_];
__device__ float g_x  [2*B_*XP_];
__device__ float g_hs2[B_*EMB_];
__device__ float g_ts2[B_*EMB_];
__device__ unsigned long long g_bar = 0ULL;

// Monotonic ticket barrier. Arrival = one RMW; spin = acquire LOADS only
// (no RMW in the poll loop -> no L2 atomic-unit serialization).
__device__ __forceinline__ void grid_barrier() {
    __syncthreads();
    if (threadIdx.x == 0) {
        __threadfence();                        // release our phase's writes
        const unsigned long long nb  = gridDim.x;
        const unsigned long long pos = atomicAdd(&g_bar, 1ULL);
        const unsigned long long target = (pos / nb + 1ULL) * nb;
        unsigned long long v = pos + 1ULL;
        while (v < target) {
            asm volatile("ld.acquire.gpu.u64 %0, [%1];"
                         : "=l"(v) : "l"(&g_bar) : "memory");
            if (v < target) __nanosleep(128);
        }
    }
    __syncthreads();
}

__device__ __forceinline__ void l2_prefetch(const void* p) {
    asm volatile("prefetch.global.L2 [%0];" :: "l"(p));
}

__global__ void __launch_bounds__(NT_, 2) fused_kernel(
    const float* __restrict__ seq,  const float* __restrict__ attn,
    const int*   __restrict__ epos,
    const float* __restrict__ hs_ner, const float* __restrict__ ts_ner,
    const float* __restrict__ Wh, const float* __restrict__ bh,
    const float* __restrict__ Wt, const float* __restrict__ bt,
    const float* __restrict__ Wb, const float* __restrict__ bb,
    float* __restrict__ out)
{
    extern __shared__ float sm[];
    const int tid = threadIdx.x;
    const int nb  = gridDim.x;

    // ======== P0: warm L2 with the weight streams (overlaps P1/P2) ========
    {
        const int gt  = blockIdx.x*NT_ + tid;
        const int gn  = nb*NT_;
        const size_t wsz = (size_t)EMB_*XDIM_;                 // 1.18M floats
        for (size_t i = (size_t)gt*32; i < wsz; i += (size_t)gn*32) {
            l2_prefetch(Wh + i);
            l2_prefetch(Wt + i);
        }
        const size_t bsz = (size_t)NCLS_*EMB_*BLK_;
        for (size_t i = (size_t)gt*32; i < bsz; i += (size_t)gn*32)
            l2_prefetch(Wb + i);
    }

    // ======== P1: ht per-head partials (flattened) + LSE embeddings ========
    {
        const int tot = B_*HEADS_*L_ + B_*HID_;   // 98304 + 12288
        for (int idx = blockIdx.x*NT_ + tid; idx < tot; idx += nb*NT_) {
            if (idx < B_*HEADS_*L_) {
                const int l  = idx & (L_-1);
                const int bh = idx >> 9;           // b*HEADS_+h
                const int b  = bh / HEADS_;
                const float* ah = attn + (size_t)bh * L_ * L_;
                float a0 = 0.f, a1 = 0.f;
#pragma unroll
                for (int m = 0; m < 4; m++) {
                    const int s0 = __ldg(&epos[b*8 + m])     + 1;
                    const int s1 = __ldg(&epos[b*8 + 4 + m]) + 1;
                    a0 += __ldg(&ah[(size_t)s0*L_ + l]);
                    a1 += __ldg(&ah[(size_t)s1*L_ + l]);
                }
                g_htp[idx] = a0 * a1 * (1.0f/192.0f);
            } else {
                const int r = idx - B_*HEADS_*L_;
                const int b = r / HID_;
                const int d = r - b*HID_;
                const float* seqb = seq + (size_t)b * L_ * HID_;
                float v0[4], v1[4];
#pragma unroll
                for (int m = 0; m < 4; m++) {
                    const int s0 = __ldg(&epos[b*8 + m])     + 1;
                    const int s1 = __ldg(&epos[b*8 + 4 + m]) + 1;
                    v0[m] = __ldg(&seqb[(size_t)s0*HID_ + d]);
                    v1[m] = __ldg(&seqb[(size_t)s1*HID_ + d]);
                }
                float mx0 = fmaxf(fmaxf(v0[0],v0[1]), fmaxf(v0[2],v0[3]));
                float mx1 = fmaxf(fmaxf(v1[0],v1[1]), fmaxf(v1[2],v1[3]));
                float e0 = __expf(v0[0]-mx0)+__expf(v0[1]-mx0)+__expf(v0[2]-mx0)+__expf(v0[3]-mx0);
                float e1 = __expf(v1[0]-mx1)+__expf(v1[1]-mx1)+__expf(v1[2]-mx1)+__expf(v1[3]-mx1);
                g_hs[b*HID_ + d] = mx0 + __logf(e0);
                g_ts[b*HID_ + d] = mx1 + __logf(e1);
            }
        }
    }
    grid_barrier();

    // ======== P2: rs chunk partials (256 items, float2, 4 l-subgroups) ========
    {
        float* sht  = sm;          // 32
        float* pacc = sm + 32;     // 4*768
        const int lg = tid >> 7;          // 0..3 (8 l each)
        const int dt = tid & 127;         // float2 column
        for (int item = blockIdx.x; item < NCHUNK_*B_; item += nb) {
            const int chunk = item / B_;
            const int b     = item % B_;
            __syncthreads();
            if (tid < 32) {
                const int l = chunk*32 + tid;
                float acc = 0.f;
#pragma unroll
                for (int h = 0; h < HEADS_; h++)
                    acc += g_htp[(b*HEADS_ + h)*L_ + l];
                sht[tid] = acc;
                float s = acc;
#pragma unroll
                for (int off = 16; off > 0; off >>= 1)
                    s += __shfl_down_sync(0xffffffffu, s, off);
                if (tid == 0) g_Sp[item] = s;
            }
            __syncthreads();
            {
                const float* seqb = seq + ((size_t)b*L_ + chunk*32 + lg*8) * HID_;
                float2 a0 = {0.f,0.f}, a1 = {0.f,0.f}, a2 = {0.f,0.f};
#pragma unroll
                for (int l = 0; l < 8; l++) {
                    const float w = sht[lg*8 + l];
                    const float* row = seqb + (size_t)l * HID_;
                    const float2 v0 = *(const float2*)&row[dt*2      ];
                    const float2 v1 = *(const float2*)&row[dt*2 + 256];
                    const float2 v2 = *(const float2*)&row[dt*2 + 512];
                    a0.x = fmaf(v0.x, w, a0.x); a0.y = fmaf(v0.y, w, a0.y);
                    a1.x = fmaf(v1.x, w, a1.x); a1.y = fmaf(v1.y, w, a1.y);
                    a2.x = fmaf(v2.x, w, a2.x); a2.y = fmaf(v2.y, w, a2.y);
                }
                float* pp = pacc + lg*768;
                *(float2*)&pp[dt*2      ] = a0;
                *(float2*)&pp[dt*2 + 256] = a1;
                *(float2*)&pp[dt*2 + 512] = a2;
            }
            __syncthreads();
            {
                float* dst = g_rsp + (size_t)item * HID_;
                for (int i = tid; i < HID_; i += NT_)
                    dst[i] = (pacc[i] + pacc[768 + i])
                           + (pacc[1536 + i] + pacc[2304 + i]);
            }
        }
    }
    grid_barrier();

    // ======== P3: build g_x = [e | rs/(S+1e-5) | ner | 0-pad] ========
    for (int idx = blockIdx.x*NT_ + tid; idx < 2*B_*XP_; idx += nb*NT_) {
        const int half = idx / (B_*XP_);
        const int rem  = idx - half*(B_*XP_);
        const int b    = rem / XP_;
        const int k    = rem - b*XP_;
        float v = 0.f;
        if (k < HID_) {
            v = half ? g_ts[b*HID_ + k] : g_hs[b*HID_ + k];
        } else if (k < 2*HID_) {
            const int d = k - HID_;
            float acc = 0.f, S = 0.f;
#pragma unroll
            for (int c = 0; c < NCHUNK_; c++) {
                acc += g_rsp[((size_t)(c*B_ + b))*HID_ + d];
                S   += g_Sp[c*B_ + b];
            }
            v = acc / (S + 1e-5f);
        } else if (k < XDIM_) {
            const int d = k - 2*HID_;
            v = half ? __ldg(&ts_ner[b*NER_ + d]) : __ldg(&hs_ner[b*NER_ + d]);
        }
        g_x[idx] = v;
    }
    grid_barrier();

    // ======== P4: hs2/ts2 = tanh(x @ W.T + b) ========
    // 384 items: (half, tile, batch-group). Each item: 8 rows x 8 batches.
    {
        float* xsh = sm;                // 8 * XP_ = 14336 floats
        float* red = sm + 8*XP_;        // 16 warps * 8
        for (int item = blockIdx.x; item < 384; item += nb) {
            const int bg     = item & 1;
            const int tile_h = item >> 1;       // 0..191
            const int half   = tile_h / 96;
            const int tile   = tile_h % 96;
            const int obase  = tile * 8;
            const float* Wsel = half ? Wt : Wh;
            const float* bias = half ? bt : bh;
            float*       outb = half ? g_ts2 : g_hs2;
            __syncthreads();
            {   // stage 8 batches of x (includes zero pad)
                const float* xsrc = g_x + ((size_t)half*B_ + bg*8) * XP_;
                for (int i = tid*4; i < 8*XP_; i += NT_*4)
                    *(float4*)&xsh[i] = *(const float4*)&xsrc[i];
            }
            __syncthreads();
            {
                const int g  = tid >> 6;        // 0..7
                const int kt = tid & 63;        // 0..63
                const int rh = g >> 1;          // 0..3 -> rows rh*2, rh*2+1
                const int bq = g & 1;           // 0..1 -> batches bq*4..bq*4+3
                const int o0 = obase + rh*2;

                float acc[2][4];
#pragma unroll
                for (int r = 0; r < 2; r++)
#pragma unroll
                    for (int j = 0; j < 4; j++) acc[r][j] = 0.f;

                const float* xb = xsh + (size_t)(bq*4) * XP_;
                const float* W0 = Wsel + (size_t)o0     * XDIM_;
                const float* W1 = Wsel + (size_t)(o0+1) * XDIM_;
#pragma unroll
                for (int it = 0; it < 14; it++) {
                    const int k = kt*2 + it*128;
                    float2 wv0 = make_float2(0.f, 0.f);
                    float2 wv1 = make_float2(0.f, 0.f);
                    if (k < XDIM_) {
                        wv0 = *(const float2*)&W0[k];
                        wv1 = *(const float2*)&W1[k];
                    }
#pragma unroll
                    for (int j = 0; j < 4; j++) {
                        const float2 xv = *(const float2*)&xb[j*XP_ + k];
                        acc[0][j] = fmaf(wv0.x, xv.x, fmaf(wv0.y, xv.y, acc[0][j]));
                        acc[1][j] = fmaf(wv1.x, xv.x, fmaf(wv1.y, xv.y, acc[1][j]));
                    }
                }
#pragma unroll
                for (int r = 0; r < 2; r++)
#pragma unroll
                    for (int j = 0; j < 4; j++)
#pragma unroll
                        for (int off = 16; off > 0; off >>= 1)
                            acc[r][j] += __shfl_down_sync(0xffffffffu, acc[r][j], off);
                if ((tid & 31) == 0) {
                    const int w = tid >> 5;     // 0..15  (= g*2 + sub)
#pragma unroll
                    for (int r = 0; r < 2; r++)
#pragma unroll
                        for (int j = 0; j < 4; j++)
                            red[w*8 + r*4 + j] = acc[r][j];
                }
            }
            __syncthreads();
            if (tid < 64) {
                const int ro = tid >> 3;       // 0..7 local row
                const int j  = tid & 7;        // 0..7 local batch
                const int rh = ro >> 1, rr = ro & 1;
                const int bq = j >> 2,  jj = j & 3;
                const int g  = rh*2 + bq;
                const float s = red[(2*g  )*8 + rr*4 + jj]
                              + red[(2*g+1)*8 + rr*4 + jj];
                const int o = obase + rh*2 + rr;
                outb[(bg*8 + j)*EMB_ + o] = tanhf(s + __ldg(&bias[o]));
            }
        }
    }
    grid_barrier();

    // ======== P5: logits (194 (class, batch-half) items) ========
    {
        float* hsh = sm;                   // 6144
        float* tsh = sm + 6144;            // 6144
        float* wsh = sm + 12288;           // 6144
        float* red = sm + 18432;           // 16*8
        for (int item = blockIdx.x; item < 2*NCLS_; item += nb) {
            const int c    = item >> 1;
            const int half = item & 1;
            __syncthreads();
            {
                const float* hsrc = g_hs2 + half*8*EMB_;
                const float* tsrc = g_ts2 + half*8*EMB_;
                const float* Wc   = Wb + (size_t)c * (EMB_*BLK_);
                for (int i = tid*4; i < 8*EMB_; i += NT_*4) {
                    *(float4*)&hsh[i] = *(const float4*)&hsrc[i];
                    *(float4*)&tsh[i] = *(const float4*)&tsrc[i];
                    *(float4*)&wsh[i] = *(const float4*)&Wc[i];
                }
            }
            __syncthreads();
            {
                float acc[8];
#pragma unroll
                for (int b = 0; b < 8; b++) acc[b] = 0.f;
#pragma unroll
                for (int g = 0; g < 3; g++) {
                    const int j = tid*4 + g*2048;
                    const float4 wv = *(const float4*)&wsh[j];
                    const int hidx  = j >> 3;
                    const int tbase = ((j >> 6) << 3) | (j & 7);
#pragma unroll
                    for (int b = 0; b < 8; b++) {
                        const float  hv = hsh[b*EMB_ + hidx];
                        const float4 tv = *(const float4*)&tsh[b*EMB_ + tbase];
                        acc[b] = fmaf(wv.x, hv*tv.x, acc[b]);
                        acc[b] = fmaf(wv.y, hv*tv.y, acc[b]);
                        acc[b] = fmaf(wv.z, hv*tv.z, acc[b]);
                        acc[b] = fmaf(wv.w, hv*tv.w, acc[b]);
                    }
                }
#pragma unroll
                for (int b = 0; b < 8; b++)
#pragma unroll
                    for (int off = 16; off > 0; off >>= 1)
                        acc[b] += __shfl_down_sync(0xffffffffu, acc[b], off);
                if ((tid & 31) == 0) {
                    const int w = tid >> 5;    // 0..15
#pragma unroll
                    for (int b = 0; b < 8; b++) red[w*8 + b] = acc[b];
                }
            }
            __syncthreads();
            if (tid < 8) {
                float s = __ldg(&bb[c]);
#pragma unroll
                for (int w2 = 0; w2 < 16; w2++) s += red[w2*8 + tid];
                out[(half*8 + tid)*NCLS_ + c] = s;
            }
        }
    }
}

// ---------------- launch ----------------
extern "C" void kernel_launch(void* const* d_in, const int* in_sizes, int n_in,
                              void* d_out, int out_size)
{
    const float* seq    = (const float*)d_in[0];
    const float* attn   = (const float*)d_in[1];
    const int*   epos   = (const int*)  d_in[2];
    const float* hs_ner = (const float*)d_in[3];
    const float* ts_ner = (const float*)d_in[4];
    const float* Wh     = (const float*)d_in[5];
    const float* bh     = (const float*)d_in[6];
    const float* Wt     = (const float*)d_in[7];
    const float* bt     = (const float*)d_in[8];
    const float* Wb     = (const float*)d_in[9];
    const float* bb     = (const float*)d_in[10];
    float* out = (float*)d_out;

    const int smem = (18432 + 128) * 4;    // 74240 B (P5 max)
    cudaFuncSetAttribute(fused_kernel, cudaFuncAttributeMaxDynamicSharedMemorySize, smem);

    int nsm = 148;
    cudaDeviceGetAttribute(&nsm, cudaDevAttrMultiProcessorCount, 0);
    int bpm = 1;
    cudaOccupancyMaxActiveBlocksPerMultiprocessor(&bpm, fused_kernel, NT_, smem);
    if (bpm < 1) bpm = 1;
    const int nb = nsm * bpm;   // all CTAs co-resident => grid barrier safe

    fused_kernel<<<nb, NT_, smem>>>(seq, attn, epos, hs_ner, ts_ner,
                                    Wh, bh, Wt, bt, Wb, bb, out);
}